// round 6
// baseline (speedup 1.0000x reference)
#include <cuda_runtime.h>
#include <cuda_fp16.h>
#include <math.h>
#include <stdint.h>

#define NDEST 8192
#define NSRC  8192
#define FEATD 1024
#define TFD   256
#define EMB   64
#define HID   128
#define HEADS 2

// scratch (static device arrays: allocation-free)
__device__ __half g_fsrc_h[(size_t)NSRC * FEATD];        // 16 MB
__device__ __half g_fcW_h[TFD * FEATD];                  // 0.5 MB
__device__ __half g_decW_h[FEATD * TFD];                 // 0.5 MB
__device__ __half g_trans_h[(size_t)NSRC * TFD];         // 4 MB
__device__ float  g_hsrc[(size_t)HEADS * NSRC * HID];    // 8 MB
__device__ float  g_q[(size_t)HEADS * NDEST * HID];      // 8 MB
__device__ float  g_wc[HEADS * EMB * HID];               // 64 KB

// ---------------------------------------------------------------------------
// f32 -> f16 conversion (n multiple of 4)
// ---------------------------------------------------------------------------
__global__ void f2h_kernel(const float* __restrict__ src,
                           __half* __restrict__ dst, int n)
{
  int i = (blockIdx.x * blockDim.x + threadIdx.x) * 4;
  if (i < n) {
    float4 v = *(const float4*)(src + i);
    *(__half2*)(dst + i)     = __floats2half2_rn(v.x, v.y);
    *(__half2*)(dst + i + 2) = __floats2half2_rn(v.z, v.w);
  }
}

// ===========================================================================
// FP16 tensor-core GEMM:  C[M,N] = A[M,K] @ B[N,K]^T (+ bias[N])
// mma.m16n8k16.f16 with fp32 accum (same 10-bit mantissa as tf32 -> same
// precision, half the instructions). BM=128, BN=64, BK=32, 256 threads,
// 8 warps (4m x 2n, warp tile 32x32). Double-buffered smem; pair-permuted
// layout: fragment = one conflict-free LDS.64. Row stride 40 u32 (bank-clean
// per 16-lane phase). Requires M%128==0, N%64==0, K%32==0.
// ===========================================================================
__device__ __forceinline__ void mma_f16(float* d, const uint32_t* a, uint2 b) {
  asm volatile(
      "mma.sync.aligned.m16n8k16.row.col.f32.f16.f16.f32 "
      "{%0,%1,%2,%3}, {%4,%5,%6,%7}, {%8,%9}, {%0,%1,%2,%3};\n"
      : "+f"(d[0]), "+f"(d[1]), "+f"(d[2]), "+f"(d[3])
      : "r"(a[0]), "r"(a[1]), "r"(a[2]), "r"(a[3]), "r"(b.x), "r"(b.y));
}

#define GSM_BYTES ((2 * 128 * 40 + 2 * 64 * 40) * 4)

template<bool HALF_OUT>
__global__ __launch_bounds__(256, 2) void h16gemm_k(
    const __half* __restrict__ A, const __half* __restrict__ B,
    const float* __restrict__ bias, void* __restrict__ Cv,
    int M, int N, int K)
{
  extern __shared__ uint32_t smdyn[];
  uint32_t (*Asm)[40] = (uint32_t(*)[40])smdyn;                  // 2 x 128
  uint32_t (*Bsm)[40] = (uint32_t(*)[40])(smdyn + 2 * 128 * 40); // 2 x 64

  const int t = threadIdx.x;
  const int lane = t & 31, w = t >> 5;
  const int wm = (w & 3) * 32, wn = (w >> 2) * 32;
  const int g = lane >> 2, c = lane & 3;
  const int row0 = blockIdx.y * 128, col0 = blockIdx.x * 64;

  // global loaders: A thread -> (row t>>1, 16-k group t&1);
  //                 B thread -> (row t>>2, group bs=bq>>1, half bl=bq&1)
  const int arow = t >> 1, as = t & 1;
  const int brow = t >> 2, bq = t & 3, bs = bq >> 1, bl = bq & 1;
  const __half* pA = A + (size_t)(row0 + arow) * K + as * 16;
  const __half* pB = B + (size_t)(col0 + brow) * K + bs * 16 + bl * 8;

  uint4 qa0 = *(const uint4*)(pA);
  uint4 qa1 = *(const uint4*)(pA + 8);
  uint4 qb  = *(const uint4*)(pB);

  // prologue: stage 0.  pair-permute: slot(s,p) = 8s + 2(p&3) + (p>>2)
  {
    uint32_t* d = &Asm[arow][as * 8];
    d[0]=qa0.x; d[2]=qa0.y; d[4]=qa0.z; d[6]=qa0.w;
    d[1]=qa1.x; d[3]=qa1.y; d[5]=qa1.z; d[7]=qa1.w;
    uint32_t* e = &Bsm[brow][bs * 8 + bl];
    e[0]=qb.x; e[2]=qb.y; e[4]=qb.z; e[6]=qb.w;
  }
  __syncthreads();

  float acc[2][4][4] = {};
  int s = 0;

  for (int k0 = 0; k0 < K; k0 += 32) {
    const bool nxt = (k0 + 32 < K);
    if (nxt) {
      qa0 = *(const uint4*)(pA + k0 + 32);
      qa1 = *(const uint4*)(pA + k0 + 40);
      qb  = *(const uint4*)(pB + k0 + 32);
    }
    const uint32_t (*Ac)[40] = Asm + s * 128;
    const uint32_t (*Bc)[40] = Bsm + s * 64;

    #pragma unroll
    for (int ks = 0; ks < 2; ks++) {
      uint32_t af[2][4];
      uint2 bf[4];
      #pragma unroll
      for (int mi = 0; mi < 2; mi++) {
        uint2 lo = *(const uint2*)&Ac[wm + mi * 16 + g][ks * 8 + 2 * c];
        uint2 hi = *(const uint2*)&Ac[wm + mi * 16 + g + 8][ks * 8 + 2 * c];
        af[mi][0] = lo.x; af[mi][1] = hi.x; af[mi][2] = lo.y; af[mi][3] = hi.y;
      }
      #pragma unroll
      for (int ni = 0; ni < 4; ni++)
        bf[ni] = *(const uint2*)&Bc[wn + ni * 8 + g][ks * 8 + 2 * c];
      #pragma unroll
      for (int mi = 0; mi < 2; mi++)
        #pragma unroll
        for (int ni = 0; ni < 4; ni++)
          mma_f16(acc[mi][ni], af[mi], bf[ni]);
    }

    if (nxt) {
      uint32_t (*An)[40] = Asm + (s ^ 1) * 128;
      uint32_t (*Bn)[40] = Bsm + (s ^ 1) * 64;
      uint32_t* d = &An[arow][as * 8];
      d[0]=qa0.x; d[2]=qa0.y; d[4]=qa0.z; d[6]=qa0.w;
      d[1]=qa1.x; d[3]=qa1.y; d[5]=qa1.z; d[7]=qa1.w;
      uint32_t* e = &Bn[brow][bs * 8 + bl];
      e[0]=qb.x; e[2]=qb.y; e[4]=qb.z; e[6]=qb.w;
      __syncthreads();
      s ^= 1;
    }
  }

  #pragma unroll
  for (int mi = 0; mi < 2; mi++) {
    int r = row0 + wm + mi * 16 + g;
    #pragma unroll
    for (int ni = 0; ni < 4; ni++) {
      int cc = col0 + wn + ni * 8 + 2 * c;
      float2 bv = *(const float2*)(bias + cc);
      float* d = acc[mi][ni];
      if (HALF_OUT) {
        __half* Ch = (__half*)Cv;
        *(__half2*)(Ch + (size_t)r * N + cc) =
            __floats2half2_rn(d[0] + bv.x, d[1] + bv.y);
        *(__half2*)(Ch + (size_t)(r + 8) * N + cc) =
            __floats2half2_rn(d[2] + bv.x, d[3] + bv.y);
      } else {
        float* Cf = (float*)Cv;
        *(float2*)(Cf + (size_t)r * N + cc) =
            make_float2(d[0] + bv.x, d[1] + bv.y);
        *(float2*)(Cf + (size_t)(r + 8) * N + cc) =
            make_float2(d[2] + bv.x, d[3] + bv.y);
      }
    }
  }
}

// ---------------------------------------------------------------------------
// fp32 SGEMM for the small score-path projections (kept fp32 for accuracy).
// ---------------------------------------------------------------------------
__global__ __launch_bounds__(256) void sgemm_k(
    const float* __restrict__ A, const float* __restrict__ B,
    float* __restrict__ C,
    int M, int N, int K, long long strideB, long long strideC)
{
  const float* Bp = B + (size_t)blockIdx.z * strideB;
  float* Cp = C + (size_t)blockIdx.z * strideC;

  __shared__ float As[16][68];
  __shared__ float Bs[16][68];

  const int t  = threadIdx.x;
  const int tx = t & 15;
  const int ty = t >> 4;
  const int row0 = blockIdx.y << 6;
  const int col0 = blockIdx.x << 6;

  const int aRow = t >> 2;
  const int aK   = (t & 3) << 2;
  const int bK   = t >> 4;
  const int bN   = (t & 15) << 2;

  float acc[4][4] = {};

  for (int k0 = 0; k0 < K; k0 += 16) {
    float4 a4 = *(const float4*)(A + (size_t)(row0 + aRow) * K + (k0 + aK));
    As[aK+0][aRow] = a4.x; As[aK+1][aRow] = a4.y;
    As[aK+2][aRow] = a4.z; As[aK+3][aRow] = a4.w;
    float4 b4 = *(const float4*)(Bp + (size_t)(k0 + bK) * N + (col0 + bN));
    *(float4*)&Bs[bK][bN] = b4;
    __syncthreads();
    #pragma unroll
    for (int k = 0; k < 16; k++) {
      float4 a = *(const float4*)&As[k][ty << 2];
      float4 b = *(const float4*)&Bs[k][tx << 2];
      acc[0][0] += a.x*b.x; acc[0][1] += a.x*b.y; acc[0][2] += a.x*b.z; acc[0][3] += a.x*b.w;
      acc[1][0] += a.y*b.x; acc[1][1] += a.y*b.y; acc[1][2] += a.y*b.z; acc[1][3] += a.y*b.w;
      acc[2][0] += a.z*b.x; acc[2][1] += a.z*b.y; acc[2][2] += a.z*b.z; acc[2][3] += a.z*b.w;
      acc[3][0] += a.w*b.x; acc[3][1] += a.w*b.y; acc[3][2] += a.w*b.z; acc[3][3] += a.w*b.w;
    }
    __syncthreads();
  }

  #pragma unroll
  for (int i = 0; i < 4; i++) {
    float4 o = make_float4(acc[i][0], acc[i][1], acc[i][2], acc[i][3]);
    *(float4*)(Cp + (size_t)(row0 + (ty<<2) + i) * N + (col0 + (tx<<2))) = o;
  }
}

// ---------------------------------------------------------------------------
// Wc[h] = att_W[h] (64x128) @ att_W2[h] (128x128)
// ---------------------------------------------------------------------------
__global__ void wc_kernel(const float* __restrict__ attW,
                          const float* __restrict__ attW2,
                          float* __restrict__ wc)
{
  int h = blockIdx.y;
  int idx = blockIdx.x * blockDim.x + threadIdx.x;
  int e = idx >> 7, d = idx & 127;
  const float* W  = attW  + h * EMB * HID + e * HID;
  const float* W2 = attW2 + h * HID * HID;
  float s = 0.f;
  #pragma unroll 8
  for (int k = 0; k < HID; k++) s += W[k] * W2[k * HID + d];
  wc[h * EMB * HID + idx] = s;
}

// ---------------------------------------------------------------------------
// Sparse masked attention, one block (512 threads) per destination row m.
// out = inv0 * sum(e0*x) + inv1 * sum(e1*x): unnormalized dual accumulators,
// no Z broadcast wait. 16 warps compute scores; gather split across two
// 256-thread groups (hf). nnz ~ 82 +/- 9; SCAP=1024 (~100 sigma); chunked
// single-pass fallback keeps correctness for nnz > SCAP (never taken).
// ---------------------------------------------------------------------------
__device__ __forceinline__ float2 score_exp_pair(
    int n, const float* qsh, const float* __restrict__ hsrc, int lane)
{
  const float4* k0 = (const float4*)(hsrc + (size_t)n * HID);
  const float4* k1 = (const float4*)(hsrc + ((size_t)NSRC + n) * HID);
  const float4 a0 = ((const float4*)qsh)[lane];
  const float4 a1 = ((const float4*)qsh)[32 + lane];
  float4 b0 = k0[lane], b1 = k1[lane];
  float s0 = a0.x*b0.x + a0.y*b0.y + a0.z*b0.z + a0.w*b0.w;
  float s1 = a1.x*b1.x + a1.y*b1.y + a1.z*b1.z + a1.w*b1.w;
  #pragma unroll
  for (int o = 16; o; o >>= 1) {
    s0 += __shfl_xor_sync(0xffffffffu, s0, o);
    s1 += __shfl_xor_sync(0xffffffffu, s1, o);
  }
  float e0 = expf(s0 > 0.f ? s0 : expm1f(s0));  // exp(elu(s))
  float e1 = expf(s1 > 0.f ? s1 : expm1f(s1));
  return make_float2(e0, e1);
}

#define SCAP 1024

__global__ __launch_bounds__(512) void attn_kernel(
    const float* __restrict__ bias,
    const float* __restrict__ q,            // [2][NDEST][HID]
    const float* __restrict__ hsrc,         // [2][NSRC][HID]
    const __half* __restrict__ xh,          // [NSRC][TFD] fp16
    float* __restrict__ out)                // [NDEST][TFD]
{
  const int m = blockIdx.x;
  const int t = threadIdx.x;                 // 0..511
  const int warp = t >> 5, lane = t & 31;
  const int col = t & 255, hf = t >> 8;

  __shared__ unsigned short sidx[SCAP];        // 2 KB
  __shared__ __align__(16) float qsh[2 * HID]; // 1 KB
  __shared__ float2 ecache[SCAP];              // 8 KB
  __shared__ int s_warp[16];
  __shared__ float sZ0, sZ1;
  __shared__ float2 pacc[256];                 // 2 KB

  if (t < 256) {
    int h = t >> 7, d = t & 127;
    qsh[t] = q[((size_t)h * NDEST + m) * HID + d];
  }

  const float4* brow4 = (const float4*)(bias + (size_t)m * NSRC);

  // count nonzeros in this thread's 16 columns; warp-shuffle scan
  float4 v[4];
  int cnt = 0;
  #pragma unroll
  for (int i = 0; i < 4; i++) {
    v[i] = brow4[t * 4 + i];
    cnt += (v[i].x>0.f)+(v[i].y>0.f)+(v[i].z>0.f)+(v[i].w>0.f);
  }
  int inc = cnt;
  #pragma unroll
  for (int o = 1; o < 32; o <<= 1) {
    int u = __shfl_up_sync(0xffffffffu, inc, o);
    if (lane >= o) inc += u;
  }
  if (lane == 31) s_warp[warp] = inc;
  __syncthreads();
  int nnz = 0, woff = 0;
  #pragma unroll
  for (int i = 0; i < 16; i++) {
    int u = s_warp[i];
    nnz += u;
    if (i < warp) woff += u;
  }

  if (nnz == 0) {
    // all masked: softmax uniform over all sources (reference behavior)
    float a = 0.f;
    for (int n = hf * (NSRC/2); n < (hf + 1) * (NSRC/2); n++)
      a += __half2float(xh[(size_t)n * TFD + col]);
    __syncthreads();
    if (hf) pacc[col] = make_float2(a, 0.f);
    __syncthreads();
    if (!hf) out[(size_t)m * TFD + col] = (a + pacc[col].x) * (1.0f / NSRC);
    return;
  }

  if (nnz <= SCAP) {
    // ---------------- fast path ----------------
    int base = woff + inc - cnt;
    #pragma unroll
    for (int i = 0; i < 4; i++) {
      int b0 = t * 16 + i * 4;
      if (v[i].x > 0.f) sidx[base++] = (unsigned short)(b0 + 0);
      if (v[i].y > 0.f) sidx[base++] = (unsigned short)(b0 + 1);
      if (v[i].z > 0.f) sidx[base++] = (unsigned short)(b0 + 2);
      if (v[i].w > 0.f) sidx[base++] = (unsigned short)(b0 + 3);
    }
    __syncthreads();

    // scores -> ecache (16 warps in parallel)
    for (int j = warp; j < nnz; j += 16) {
      float2 e = score_exp_pair(sidx[j], qsh, hsrc, lane);
      if (lane == 0) ecache[j] = e;
    }
    __syncthreads();

    // warp 0 computes Z while everyone gathers
    if (warp == 0) {
      float z0 = 0.f, z1 = 0.f;
      for (int j = lane; j < nnz; j += 32) {
        float2 e = ecache[j];
        z0 += e.x; z1 += e.y;
      }
      #pragma unroll
      for (int o = 16; o; o >>= 1) {
        z0 += __shfl_xor_sync(0xffffffffu, z0, o);
        z1 += __shfl_xor_sync(0xffffffffu, z1, o);
      }
      if (lane == 0) { sZ0 = z0; sZ1 = z1; }
    }

    // unnormalized dual-accumulator gather, split halves across hf groups
    const int half = nnz >> 1;
    const int j0 = hf ? half : 0;
    const int j1 = hf ? nnz : half;
    float acc0 = 0.f, acc1 = 0.f;
    int j = j0;
    for (; j + 4 <= j1; j += 4) {
      float2 e0 = ecache[j+0], e1 = ecache[j+1];
      float2 e2 = ecache[j+2], e3 = ecache[j+3];
      float x0 = __half2float(xh[(size_t)sidx[j+0] * TFD + col]);
      float x1 = __half2float(xh[(size_t)sidx[j+1] * TFD + col]);
      float x2 = __half2float(xh[(size_t)sidx[j+2] * TFD + col]);
      float x3 = __half2float(xh[(size_t)sidx[j+3] * TFD + col]);
      acc0 += e0.x*x0 + e1.x*x1 + e2.x*x2 + e3.x*x3;
      acc1 += e0.y*x0 + e1.y*x1 + e2.y*x2 + e3.y*x3;
    }
    for (; j < j1; j++) {
      float2 e = ecache[j];
      float x = __half2float(xh[(size_t)sidx[j] * TFD + col]);
      acc0 += e.x * x; acc1 += e.y * x;
    }
    __syncthreads();
    if (hf) pacc[col] = make_float2(acc0, acc1);
    __syncthreads();
    if (!hf) {
      float2 p = pacc[col];
      out[(size_t)m * TFD + col] =
          (acc0 + p.x) * (0.5f / sZ0) + (acc1 + p.y) * (0.5f / sZ1);
    }
    return;
  }

  // -------- fallback: nnz > SCAP, chunked single pass (never expected) -----
  float acc0 = 0.f, acc1 = 0.f;
  float zp0 = 0.f, zp1 = 0.f;  // warp 0 lanes only
  for (int c0 = 0; c0 < NSRC; c0 += SCAP) {
    __syncthreads();  // protect sidx/ecache reuse
    float2 w2 = *(const float2*)(bias + (size_t)m * NSRC + c0 + t * 2);
    int ccnt = (w2.x > 0.f) + (w2.y > 0.f);
    int cinc = ccnt;
    #pragma unroll
    for (int o = 1; o < 32; o <<= 1) {
      int u = __shfl_up_sync(0xffffffffu, cinc, o);
      if (lane >= o) cinc += u;
    }
    if (lane == 31) s_warp[warp] = cinc;
    __syncthreads();
    int cn = 0, cwoff = 0;
    #pragma unroll
    for (int i = 0; i < 16; i++) {
      int u = s_warp[i];
      cn += u;
      if (i < warp) cwoff += u;
    }
    int base = cwoff + cinc - ccnt;
    int b0 = c0 + t * 2;
    if (w2.x > 0.f) sidx[base++] = (unsigned short)(b0 + 0);
    if (w2.y > 0.f) sidx[base++] = (unsigned short)(b0 + 1);
    __syncthreads();

    for (int j = warp; j < cn; j += 16) {
      float2 e = score_exp_pair(sidx[j], qsh, hsrc, lane);
      if (lane == 0) ecache[j] = e;
    }
    __syncthreads();

    if (warp == 0) {
      for (int j = lane; j < cn; j += 32) {
        float2 e = ecache[j];
        zp0 += e.x; zp1 += e.y;
      }
    }
    const int chalf = cn >> 1;
    const int j0 = hf ? chalf : 0;
    const int j1 = hf ? cn : chalf;
    for (int j = j0; j < j1; j++) {
      float2 e = ecache[j];
      float x = __half2float(xh[(size_t)sidx[j] * TFD + col]);
      acc0 += e.x * x; acc1 += e.y * x;
    }
  }
  if (warp == 0) {
    #pragma unroll
    for (int o = 16; o; o >>= 1) {
      zp0 += __shfl_xor_sync(0xffffffffu, zp0, o);
      zp1 += __shfl_xor_sync(0xffffffffu, zp1, o);
    }
    if (lane == 0) { sZ0 = zp0; sZ1 = zp1; }
  }
  __syncthreads();
  if (hf) pacc[col] = make_float2(acc0, acc1);
  __syncthreads();
  if (!hf) {
    float2 p = pacc[col];
    out[(size_t)m * TFD + col] =
        (acc0 + p.x) * (0.5f / sZ0) + (acc1 + p.y) * (0.5f / sZ1);
  }
}

// ---------------------------------------------------------------------------
extern "C" void kernel_launch(void* const* d_in, const int* in_sizes, int n_in,
                              void* d_out, int out_size)
{
  const float* bias        = (const float*)d_in[0];
  const float* emb_dest    = (const float*)d_in[1];
  const float* emb_src     = (const float*)d_in[2];
  const float* feature_src = (const float*)d_in[3];
  const float* fc_W        = (const float*)d_in[4];
  const float* fc_b        = (const float*)d_in[5];
  const float* dec_W       = (const float*)d_in[6];
  const float* dec_b       = (const float*)d_in[7];
  const float* att_W       = (const float*)d_in[8];
  const float* att_W2      = (const float*)d_in[9];

  float* out_re  = (float*)d_out;
  float* out_hat = out_re + (size_t)NDEST * TFD;

  __half *fsrc_h, *fcW_h, *decW_h, *trans_h;
  float *hsrc, *qp, *wc;
  cudaGetSymbolAddress((void**)&fsrc_h, g_fsrc_h);
  cudaGetSymbolAddress((void**)&fcW_h, g_fcW_h);
  cudaGetSymbolAddress((void**)&decW_h, g_decW_h);
  cudaGetSymbolAddress((void**)&trans_h, g_trans_h);
  cudaGetSymbolAddress((void**)&hsrc, g_hsrc);
  cudaGetSymbolAddress((void**)&qp, g_q);
  cudaGetSymbolAddress((void**)&wc, g_wc);

  cudaFuncSetAttribute(h16gemm_k<true>,
                       cudaFuncAttributeMaxDynamicSharedMemorySize, GSM_BYTES);
  cudaFuncSetAttribute(h16gemm_k<false>,
                       cudaFuncAttributeMaxDynamicSharedMemorySize, GSM_BYTES);

  // input conversions to fp16
  {
    int n1 = NSRC * FEATD;
    f2h_kernel<<<(n1/4 + 255)/256, 256>>>(feature_src, fsrc_h, n1);
    int n2 = TFD * FEATD;
    f2h_kernel<<<(n2/4 + 255)/256, 256>>>(fc_W, fcW_h, n2);
    int n3 = FEATD * TFD;
    f2h_kernel<<<(n3/4 + 255)/256, 256>>>(dec_W, decW_h, n3);
  }

  // Wc[h] = att_W[h] @ att_W2[h]
  wc_kernel<<<dim3(32, 2), 256>>>(att_W, att_W2, wc);

  // h_src[h] = emb_src @ att_W[h]   (fp32 for score accuracy)
  sgemm_k<<<dim3(HID / 64, NSRC / 64, HEADS), 256>>>(
      emb_src, att_W, hsrc, NSRC, HID, EMB,
      (long long)EMB * HID, (long long)NSRC * HID);

  // q[h] = emb_dest @ Wc[h]
  sgemm_k<<<dim3(HID / 64, NDEST / 64, HEADS), 256>>>(
      emb_dest, wc, qp, NDEST, HID, EMB,
      (long long)EMB * HID, (long long)NDEST * HID);

  // transformed = feature_src @ fc_W^T + fc_b   (fp16 mma, half output)
  h16gemm_k<true><<<dim3(TFD / 64, NSRC / 128), 256, GSM_BYTES>>>(
      fsrc_h, fcW_h, fc_b, trans_h, NSRC, TFD, FEATD);

  // feature_hat = transformed @ dec_W^T + dec_b (fp16 mma, float output)
  h16gemm_k<false><<<dim3(FEATD / 64, NSRC / 128), 256, GSM_BYTES>>>(
      trans_h, decW_h, dec_b, out_hat, NSRC, FEATD, TFD);

  // sparse masked attention + aggregation
  attn_kernel<<<NDEST, 512>>>(bias, qp, hsrc, trans_h, out_re);
}